// round 12
// baseline (speedup 1.0000x reference)
#include <cuda_runtime.h>
#include <cstdint>

// Problem constants
#define NB      8
#define NS      8192
#define DIM     1024
#define NE      16
#define NTOK    (NB * NS)          // 65536 tokens

#define M_TILE   64                // tokens per block (16 per warp, 4 warps)
#define THREADS  128
#define GRID     (NTOK / M_TILE)   // 1024 blocks

// Ambiguity margin for top-2 selection (logit scale). Split-TF32 noise ~1e-5;
// gaps below this are re-arbitrated in exact fp32.
#define GUARD_EPS 5e-3f

// Mask split: hi = v with low 13 mantissa bits cleared (exact tf32),
// lo = v - hi (exact in fp32; MMA truncates lo's tail -> err ~2^-24 |v|).
static __device__ __forceinline__ void split_mask(float v, uint32_t& hi, uint32_t& lo) {
    const uint32_t h = __float_as_uint(v) & 0xFFFFE000u;
    hi = h;
    lo = __float_as_uint(v - __uint_as_float(h));
}

static __device__ __forceinline__ void mma_tf32(float d[4],
                                                uint32_t a0, uint32_t a1,
                                                uint32_t a2, uint32_t a3,
                                                uint32_t b0, uint32_t b1) {
    asm volatile(
        "mma.sync.aligned.m16n8k8.row.col.f32.tf32.tf32.f32 "
        "{%0,%1,%2,%3}, {%4,%5,%6,%7}, {%8,%9}, {%0,%1,%2,%3};"
        : "+f"(d[0]), "+f"(d[1]), "+f"(d[2]), "+f"(d[3])
        : "r"(a0), "r"(a1), "r"(a2), "r"(a3), "r"(b0), "r"(b1));
}

__global__ __launch_bounds__(THREADS, 6) void gating_mma_kernel(
    const float* __restrict__ x,
    const float* __restrict__ W,
    const float* __restrict__ bias,
    float* __restrict__ out)
{
    __shared__ float sLog[THREADS / 32][16][NE];   // 4KB, epilogue staging

    const int tid  = threadIdx.x;
    const int wid  = tid >> 5;
    const int lane = tid & 31;
    const int g    = lane >> 2;        // fragment group 0..7
    const int tg   = lane & 3;         // thread-in-group 0..3
    const int tokw = blockIdx.x * M_TILE + wid * 16;   // warp's 16-token base

    // K-PERMUTED fragments: for k8 group p, thread's K pair = {4tg+2p, 4tg+2p+1}.
    // Same per-thread permutation on A and B -> sum over K unchanged (exact).
    const float* xa = x + (size_t)(tokw + g) * DIM + 4 * tg;  // A rows g, g+8
    const float* wb = W + (size_t)g * DIM + 4 * tg;           // B experts g, g+8

    float acc[2][4];                   // [n-tile][frag]
    #pragma unroll
    for (int j = 0; j < 2; j++)
        #pragma unroll
        for (int c = 0; c < 4; c++) acc[j][c] = 0.0f;

    #pragma unroll 2
    for (int k = 0; k < DIM; k += 16) {
        // 4 independent LDG.128 per thread (2 A rows, 2 B rows)
        float4 a[2], b[2];
        a[0] = *(const float4*)(xa + k);             // token row g
        a[1] = *(const float4*)(xa + 8 * DIM + k);   // token row g+8
        b[0] = *(const float4*)(wb + k);             // experts 0..7 slice
        b[1] = *(const float4*)(wb + 8 * DIM + k);   // experts 8..15 slice

        uint32_t ah[2][4], al[2][4], bh[2][4], bl[2][4];
        #pragma unroll
        for (int r = 0; r < 2; r++) {
            split_mask(a[r].x, ah[r][0], al[r][0]);
            split_mask(a[r].y, ah[r][1], al[r][1]);
            split_mask(a[r].z, ah[r][2], al[r][2]);
            split_mask(a[r].w, ah[r][3], al[r][3]);
            split_mask(b[r].x, bh[r][0], bl[r][0]);
            split_mask(b[r].y, bh[r][1], bl[r][1]);
            split_mask(b[r].z, bh[r][2], bl[r][2]);
            split_mask(b[r].w, bh[r][3], bl[r][3]);
        }

        #pragma unroll
        for (int p = 0; p < 2; p++) {          // two k8 groups per k16
            const int c0 = 2 * p, c1 = 2 * p + 1;
            #pragma unroll
            for (int nt = 0; nt < 2; nt++) {
                float* d = acc[nt];
                // 3-term split TF32: hh + lh + hl (err ~1e-5; selection guarded)
                mma_tf32(d, ah[0][c0], ah[1][c0], ah[0][c1], ah[1][c1],
                            bh[nt][c0], bh[nt][c1]);
                mma_tf32(d, al[0][c0], al[1][c0], al[0][c1], al[1][c1],
                            bh[nt][c0], bh[nt][c1]);
                mma_tf32(d, ah[0][c0], ah[1][c0], ah[0][c1], ah[1][c1],
                            bl[nt][c0], bl[nt][c1]);
            }
        }
    }

    // Scatter accumulators: D row g/g+8 = token-in-warp, col 2tg/2tg+1 (+8nt).
    #pragma unroll
    for (int nt = 0; nt < 2; nt++) {
        sLog[wid][g    ][nt * 8 + 2 * tg    ] = acc[nt][0];
        sLog[wid][g    ][nt * 8 + 2 * tg + 1] = acc[nt][1];
        sLog[wid][g + 8][nt * 8 + 2 * tg    ] = acc[nt][2];
        sLog[wid][g + 8][nt * 8 + 2 * tg + 1] = acc[nt][3];
    }
    __syncthreads();

    // Epilogue: threads 0..63, thread t owns token blockbase + t (coalesced).
    if (tid < M_TILE) {
        const int token = blockIdx.x * M_TILE + tid;
        const float* my = sLog[tid >> 4][tid & 15];

        float lg[NE];
        float mx = -1e30f;
        #pragma unroll
        for (int e = 0; e < NE; e++) {
            lg[e] = my[e] + __ldg(&bias[e]);
            mx = fmaxf(mx, lg[e]);
        }
        float s = 0.0f;
        #pragma unroll
        for (int e = 0; e < NE; e++) { lg[e] = __expf(lg[e] - mx); s += lg[e]; }
        const float inv = 1.0f / s;

        // top-3 on logits; strict > keeps first index on ties (jax top_k).
        float raw[NE];
        #pragma unroll
        for (int e = 0; e < NE; e++) raw[e] = my[e] + __ldg(&bias[e]);

        int i1 = 0; float m1 = raw[0];
        #pragma unroll
        for (int e = 1; e < NE; e++) if (raw[e] > m1) { m1 = raw[e]; i1 = e; }
        int i2 = -1; float m2 = -1e30f;
        #pragma unroll
        for (int e = 0; e < NE; e++) if (e != i1 && raw[e] > m2) { m2 = raw[e]; i2 = e; }
        int i3 = -1; float m3 = -1e30f;
        #pragma unroll
        for (int e = 0; e < NE; e++)
            if (e != i1 && e != i2 && raw[e] > m3) { m3 = raw[e]; i3 = e; }

        // Guard: if 2nd vs 3rd within split-TF32 noise, arbitrate in exact fp32.
        int sel2 = i2;
        if (m2 - m3 < GUARD_EPS) {
            const float4* xr = (const float4*)(x + (size_t)token * DIM);
            const float4* w2 = (const float4*)(W + (size_t)i2 * DIM);
            const float4* w3 = (const float4*)(W + (size_t)i3 * DIM);
            float s2 = 0.0f, s3 = 0.0f;
            for (int q = 0; q < DIM / 4; q++) {
                const float4 xv = xr[q], a2 = w2[q], a3 = w3[q];
                s2 = fmaf(xv.x, a2.x, s2); s2 = fmaf(xv.y, a2.y, s2);
                s2 = fmaf(xv.z, a2.z, s2); s2 = fmaf(xv.w, a2.w, s2);
                s3 = fmaf(xv.x, a3.x, s3); s3 = fmaf(xv.y, a3.y, s3);
                s3 = fmaf(xv.z, a3.z, s3); s3 = fmaf(xv.w, a3.w, s3);
            }
            s2 += __ldg(&bias[i2]); s3 += __ldg(&bias[i3]);
            // Exact ranking; tie (==) keeps lower index like jax top_k.
            if (s3 > s2 || (s3 == s2 && i3 < i2)) sel2 = i3;
        }

        float* gated = out;                         // [NE, NB, NS]
        float* wout  = out + (size_t)NE * NTOK;     // [NE, NB, NS]
        #pragma unroll
        for (int e = 0; e < NE; e++) {
            const float w = lg[e] * inv;
            wout [(size_t)e * NTOK + token] = w;
            gated[(size_t)e * NTOK + token] = (e == i1 || e == sel2) ? w : 0.0f;
        }
    }
}

extern "C" void kernel_launch(void* const* d_in, const int* in_sizes, int n_in,
                              void* d_out, int out_size)
{
    (void)in_sizes; (void)n_in; (void)out_size;
    const float* x = (const float*)d_in[0];
    const float* W = (const float*)d_in[1];
    const float* b = (const float*)d_in[2];
    float* out = (float*)d_out;

    gating_mma_kernel<<<GRID, THREADS>>>(x, W, b, out);
}